// round 6
// baseline (speedup 1.0000x reference)
#include <cuda_runtime.h>
#include <cuda_bf16.h>
#include <cstdint>

// Problem constants
#define BB 2
#define SS 2048
#define HID 1024
#define MLPD 2048
#define NST 16
#define DTR 64
#define CONVK 4
#define MM (BB * SS)          // 4096 rows
#define XPW (DTR + 2 * NST)   // 96

// Scratch (device globals — no allocation allowed)
__device__ float g_uraw[(size_t)MM * MLPD];
__device__ float g_u[(size_t)MM * MLPD];
__device__ float g_gate[(size_t)MM * MLPD];
__device__ float g_delta[(size_t)MM * MLPD];
__device__ float g_xp[(size_t)MM * XPW];
__device__ float g_yg[(size_t)MM * MLPD];

// ---------------------------------------------------------------------------
// Generic fp32 SMEM-tiled GEMM: C[M,N] = A[M,K] * B[K,N]  (+ epilogue)
// BM=BN=128, BK=8, 256 threads, 8x8 microtile.
// Requirements: M % 128 == 0, K % 8 == 0, N % 4 == 0 (all hold here).
// gridDim.z = split-K factor (K % (8*gridDim.z) == 0).
// ---------------------------------------------------------------------------
#define EPI_BIAS 0
#define EPI_SIG 1
#define EPI_SOFTPLUS 2
#define EPI_ATOMIC 3

template <int EPI>
__global__ __launch_bounds__(256) void gemm128(
    const float* __restrict__ A, const float* __restrict__ B,
    const float* __restrict__ bias, float* __restrict__ C,
    int M, int N, int K, int lda, int ldb, int ldc) {
  __shared__ float As[8][128];
  __shared__ float Bs[8][128];

  const int tid = threadIdx.x;
  const int rowBase = blockIdx.y * 128;
  const int colBase = blockIdx.x * 128;
  const int kChunk = K / gridDim.z;
  const int k0g = blockIdx.z * kChunk;
  const int kEnd = k0g + kChunk;

  const int aRow = tid >> 1;         // 0..127
  const int aCol = (tid & 1) * 4;    // 0 or 4
  const int bRow = tid >> 5;         // 0..7
  const int bCol = (tid & 31) * 4;   // 0..124

  const int tx = tid & 15;
  const int ty = tid >> 4;

  float acc[8][8];
#pragma unroll
  for (int i = 0; i < 8; i++)
#pragma unroll
    for (int j = 0; j < 8; j++) acc[i][j] = 0.f;

  for (int k0 = k0g; k0 < kEnd; k0 += 8) {
    // A tile (rows always in range: M % 128 == 0)
    float4 av = *(const float4*)(A + (size_t)(rowBase + aRow) * lda + k0 + aCol);
    As[aCol + 0][aRow] = av.x;
    As[aCol + 1][aRow] = av.y;
    As[aCol + 2][aRow] = av.z;
    As[aCol + 3][aRow] = av.w;
    // B tile (N % 4 == 0, so float4 granularity guard is exact)
    float4 bv = make_float4(0.f, 0.f, 0.f, 0.f);
    if (colBase + bCol < N)
      bv = *(const float4*)(B + (size_t)(k0 + bRow) * ldb + colBase + bCol);
    *(float4*)&Bs[bRow][bCol] = bv;
    __syncthreads();

#pragma unroll
    for (int kk = 0; kk < 8; kk++) {
      float4 a01 = *(const float4*)&As[kk][ty * 8];
      float4 a23 = *(const float4*)&As[kk][ty * 8 + 4];
      float4 b01 = *(const float4*)&Bs[kk][tx * 8];
      float4 b23 = *(const float4*)&Bs[kk][tx * 8 + 4];
      float ar[8] = {a01.x, a01.y, a01.z, a01.w, a23.x, a23.y, a23.z, a23.w};
      float br[8] = {b01.x, b01.y, b01.z, b01.w, b23.x, b23.y, b23.z, b23.w};
#pragma unroll
      for (int i = 0; i < 8; i++)
#pragma unroll
        for (int j = 0; j < 8; j++) acc[i][j] = fmaf(ar[i], br[j], acc[i][j]);
    }
    __syncthreads();
  }

  // Epilogue
#pragma unroll
  for (int i = 0; i < 8; i++) {
    int row = rowBase + ty * 8 + i;
#pragma unroll
    for (int jv = 0; jv < 2; jv++) {
      int col = colBase + tx * 8 + jv * 4;
      if (col >= N) continue;
      if (EPI == EPI_ATOMIC) {
#pragma unroll
        for (int j = 0; j < 4; j++)
          atomicAdd(&C[(size_t)row * ldc + col + j], acc[i][jv * 4 + j]);
      } else {
        float4 out;
        float* o = &out.x;
#pragma unroll
        for (int j = 0; j < 4; j++) {
          float v = acc[i][jv * 4 + j] + bias[col + j];
          if (EPI == EPI_SIG) {
            v = 1.f / (1.f + __expf(-v));
          } else if (EPI == EPI_SOFTPLUS) {
            v = (v > 20.f) ? v : log1pf(__expf(v));
          }
          o[j] = v;
        }
        *(float4*)&C[(size_t)row * ldc + col] = out;
      }
    }
  }
}

// ---------------------------------------------------------------------------
// Causal depthwise conv (K=4) + sigmoid
// ---------------------------------------------------------------------------
__global__ void conv_kernel(const float* __restrict__ uraw,
                            const float* __restrict__ conv_w,
                            const float* __restrict__ conv_b,
                            float* __restrict__ u) {
  int idx = blockIdx.x * blockDim.x + threadIdx.x;
  const int total = MM * MLPD;
  if (idx >= total) return;
  int d = idx % MLPD;
  int s = (idx / MLPD) % SS;
  float acc = conv_b[d];
#pragma unroll
  for (int k = 0; k < CONVK; k++) {
    int sp = s - (CONVK - 1) + k;
    if (sp >= 0) acc = fmaf(uraw[(size_t)idx + (size_t)(k - (CONVK - 1)) * MLPD],
                            conv_w[d * CONVK + k], acc);
  }
  u[idx] = 1.f / (1.f + __expf(-acc));
}

__global__ void zero_kernel(float* __restrict__ p, int n) {
  int i = blockIdx.x * blockDim.x + threadIdx.x;
  if (i < n) p[i] = 0.f;
}

// ---------------------------------------------------------------------------
// Selective scan. 16 lanes per channel (one per state n); shfl-tree reduce.
// Fuses the D-skip and gate multiply:  yg = (scan_y + u*D) * gate
// ---------------------------------------------------------------------------
__global__ __launch_bounds__(128) void scan_kernel(
    const float* __restrict__ u, const float* __restrict__ delta,
    const float* __restrict__ xp, const float* __restrict__ A_log,
    const float* __restrict__ D_skip, const float* __restrict__ gate,
    float* __restrict__ yg) {
  const int lane_n = threadIdx.x & 15;
  const int dg = threadIdx.x >> 4;                 // 0..7
  const int d = blockIdx.x * 8 + dg;               // channel
  const int b = blockIdx.y;                        // batch

  const float A = -__expf(A_log[d * NST + lane_n]);
  const float Dv = D_skip[d];

  const size_t rowOff = (size_t)b * SS * MLPD + d;
  const float* __restrict__ xpB = xp + (size_t)b * SS * XPW;

  float h = 0.f;
#pragma unroll 4
  for (int t = 0; t < SS; t++) {
    size_t idx = rowOff + (size_t)t * MLPD;
    float dt = delta[idx];
    float ut = u[idx];
    float Bv = xpB[t * XPW + DTR + lane_n];
    float Cv = xpB[t * XPW + DTR + NST + lane_n];
    float a = __expf(dt * A);
    h = fmaf(a, h, dt * Bv * ut);
    float yp = h * Cv;
    yp += __shfl_xor_sync(0xFFFFFFFFu, yp, 8);
    yp += __shfl_xor_sync(0xFFFFFFFFu, yp, 4);
    yp += __shfl_xor_sync(0xFFFFFFFFu, yp, 2);
    yp += __shfl_xor_sync(0xFFFFFFFFu, yp, 1);
    if (lane_n == 0) {
      yg[idx] = (yp + ut * Dv) * gate[idx];
    }
  }
}

// ---------------------------------------------------------------------------
// Launch
// ---------------------------------------------------------------------------
extern "C" void kernel_launch(void* const* d_in, const int* in_sizes, int n_in,
                              void* d_out, int out_size) {
  const float* x = (const float*)d_in[0];         // (B,S,HID)
  const float* W1 = (const float*)d_in[1];        // (HID,MLP)
  const float* b1 = (const float*)d_in[2];
  const float* W2 = (const float*)d_in[3];
  const float* b2 = (const float*)d_in[4];
  const float* conv_w = (const float*)d_in[5];    // (MLP,4)
  const float* conv_b = (const float*)d_in[6];
  const float* A_log = (const float*)d_in[7];     // (MLP,16)
  const float* x_proj_w = (const float*)d_in[8];  // (MLP,96)
  const float* dt_proj_w = (const float*)d_in[9]; // (64,MLP)
  const float* dt_proj_b = (const float*)d_in[10];
  const float* D_skip = (const float*)d_in[11];
  const float* Wo = (const float*)d_in[12];       // (MLP,HID)
  const float* bo = (const float*)d_in[13];
  float* out = (float*)d_out;

  float *p_uraw, *p_u, *p_gate, *p_delta, *p_xp, *p_yg;
  cudaGetSymbolAddress((void**)&p_uraw, g_uraw);
  cudaGetSymbolAddress((void**)&p_u, g_u);
  cudaGetSymbolAddress((void**)&p_gate, g_gate);
  cudaGetSymbolAddress((void**)&p_delta, g_delta);
  cudaGetSymbolAddress((void**)&p_xp, g_xp);
  cudaGetSymbolAddress((void**)&p_yg, g_yg);

  // 1) u_raw = x @ W1 + b1      (M=4096, N=2048, K=1024)
  gemm128<EPI_BIAS><<<dim3(16, 32, 1), 256>>>(x, W1, b1, p_uraw,
                                              MM, MLPD, HID, HID, MLPD, MLPD);
  // 2) gate = sigmoid(x @ W2 + b2)
  gemm128<EPI_SIG><<<dim3(16, 32, 1), 256>>>(x, W2, b2, p_gate,
                                             MM, MLPD, HID, HID, MLPD, MLPD);
  // 3) u = sigmoid(causal_conv(u_raw))
  conv_kernel<<<(MM * MLPD + 255) / 256, 256>>>(p_uraw, conv_w, conv_b, p_u);
  // 4) xp = u @ x_proj_w   (split-K=8, atomic accumulate)
  zero_kernel<<<(MM * XPW + 255) / 256, 256>>>(p_xp, MM * XPW);
  gemm128<EPI_ATOMIC><<<dim3(1, 32, 8), 256>>>(p_u, x_proj_w, nullptr, p_xp,
                                               MM, XPW, MLPD, MLPD, XPW, XPW);
  // 5) delta = softplus(xp[:, :64] @ dt_proj_w + dt_proj_b)
  gemm128<EPI_SOFTPLUS><<<dim3(16, 32, 1), 256>>>(p_xp, dt_proj_w, dt_proj_b,
                                                  p_delta, MM, MLPD, DTR,
                                                  XPW, MLPD, MLPD);
  // 6) selective scan -> yg = (y + u*D) * gate
  scan_kernel<<<dim3(MLPD / 8, BB), 128>>>(p_u, p_delta, p_xp, A_log, D_skip,
                                           p_gate, p_yg);
  // 7) out = yg @ Wo + bo   (M=4096, N=1024, K=2048)
  gemm128<EPI_BIAS><<<dim3(8, 32, 1), 256>>>(p_yg, Wo, bo, out,
                                             MM, HID, MLPD, MLPD, HID, HID);
}

// round 9
// speedup vs baseline: 1.6032x; 1.6032x over previous
#include <cuda_runtime.h>
#include <cuda_bf16.h>
#include <cstdint>

// Problem constants
#define BB 2
#define SS 2048
#define HID 1024
#define MLPD 2048
#define NST 16
#define DTR 64
#define CONVK 4
#define MM (BB * SS)          // 4096 rows
#define XPW (DTR + 2 * NST)   // 96

// Scratch (device globals — no allocation allowed)
__device__ float g_uraw[(size_t)MM * MLPD];
__device__ float g_u[(size_t)MM * MLPD];
__device__ float g_gate[(size_t)MM * MLPD];
__device__ float g_delta[(size_t)MM * MLPD];
__device__ float g_xp[(size_t)MM * XPW];
__device__ float g_yg[(size_t)MM * MLPD];

#define EPI_BIAS 0
#define EPI_SIG 1
#define EPI_SOFTPLUS 2
#define EPI_ATOMIC 3

// ---------------------------------------------------------------------------
// tf32 tensor-core GEMM: C[M,N] = A[M,K] * B[K,N] (+ bias/activation epilogue)
// Block tile 128x128x32, 256 threads, 8 warps; warp tile 64x32 via m16n8k8.
// Double-buffered dynamic SMEM. Requires M%128==0, N%128==0, K%32==0.
// A SMEM layout: [m][k], row stride 36 floats (conflict-free frag reads).
// B SMEM layout: [k][n], row stride 132 floats (conflict-free frag reads).
// tf32 rounding (cvt.rna) applied at SMEM-store time.
// A loads: each thread owns 16 consecutive floats (half a 32-wide k-row):
//   aRow = tid>>1 (0..127), aKb = (tid&1)*16, four float4s at +0/+4/+8/+12.
//   256 threads * 16 floats = 4096 = full 128x32 tile.   (R8 fix: was 8/thread)
// B loads: bRow = tid>>3 (0..31), bNb = (tid&7)*4, four float4s at +32c.
//   256 threads * 16 floats = 4096 = full 32x128 tile.
// ---------------------------------------------------------------------------
#define ASTRIDE 36
#define BSTRIDE 132
#define ASZ (128 * ASTRIDE)       // 4608 floats
#define BSZ (32 * BSTRIDE)        // 4224 floats
#define BUFSZ (ASZ + BSZ)         // 8832 floats per buffer
#define GSMEM_BYTES (2 * BUFSZ * 4)  // 70656 bytes

__device__ __forceinline__ float f2tf32(float f) {
  uint32_t r;
  asm("cvt.rna.tf32.f32 %0, %1;" : "=r"(r) : "f"(f));
  return __uint_as_float(r);
}

__device__ __forceinline__ void mma_tf32(float* c, const uint32_t* a,
                                         const uint32_t* b) {
  asm volatile(
      "mma.sync.aligned.m16n8k8.row.col.f32.tf32.tf32.f32 "
      "{%0,%1,%2,%3}, {%4,%5,%6,%7}, {%8,%9}, {%0,%1,%2,%3};"
      : "+f"(c[0]), "+f"(c[1]), "+f"(c[2]), "+f"(c[3])
      : "r"(a[0]), "r"(a[1]), "r"(a[2]), "r"(a[3]), "r"(b[0]), "r"(b[1]));
}

template <int EPI>
__global__ __launch_bounds__(256) void gemm_tf32(
    const float* __restrict__ A, const float* __restrict__ B,
    const float* __restrict__ bias, float* __restrict__ C,
    int M, int N, int K, int lda, int ldb, int ldc) {
  extern __shared__ float sm[];

  const int tid = threadIdx.x;
  const int rowBase = blockIdx.y * 128;
  const int colBase = blockIdx.x * 128;

  const int lane = tid & 31;
  const int g = lane >> 2;   // 0..7
  const int tg = lane & 3;   // 0..3
  const int wid = tid >> 5;  // 0..7
  const int wm = wid & 1;    // 2 warps along M (64 each)
  const int wn = wid >> 1;   // 4 warps along N (32 each)

  // gmem load mapping
  const int aRow = tid >> 1;          // 0..127
  const int aKb = (tid & 1) * 16;     // 0 or 16
  const int bRow = tid >> 3;          // 0..31
  const int bNb = (tid & 7) * 4;      // 0..28

  float acc[4][4][4];
#pragma unroll
  for (int i = 0; i < 4; i++)
#pragma unroll
    for (int j = 0; j < 4; j++)
#pragma unroll
      for (int q = 0; q < 4; q++) acc[i][j][q] = 0.f;

  const int nT = K / 32;

  float4 a_stg[4], b_stg[4];

  // --- prologue: tile 0 gmem -> regs -> smem buf0 ---
  {
    const float* Ap = A + (size_t)(rowBase + aRow) * lda + aKb;
#pragma unroll
    for (int c = 0; c < 4; c++) a_stg[c] = *(const float4*)(Ap + 4 * c);
    const float* Bp = B + (size_t)bRow * ldb + colBase + bNb;
#pragma unroll
    for (int c = 0; c < 4; c++) b_stg[c] = *(const float4*)(Bp + 32 * c);

    float* As = sm;
    float* Bs = sm + ASZ;
#pragma unroll
    for (int c = 0; c < 4; c++) {
      float4 v = a_stg[c];
      float4 w = make_float4(f2tf32(v.x), f2tf32(v.y), f2tf32(v.z), f2tf32(v.w));
      *(float4*)&As[aRow * ASTRIDE + aKb + 4 * c] = w;
    }
#pragma unroll
    for (int c = 0; c < 4; c++) {
      float4 v = b_stg[c];
      float4 w = make_float4(f2tf32(v.x), f2tf32(v.y), f2tf32(v.z), f2tf32(v.w));
      *(float4*)&Bs[bRow * BSTRIDE + bNb + 32 * c] = w;
    }
    __syncthreads();
  }

  for (int t = 0; t < nT; t++) {
    // prefetch tile t+1 into regs
    if (t + 1 < nT) {
      int k0 = (t + 1) * 32;
      const float* Ap = A + (size_t)(rowBase + aRow) * lda + k0 + aKb;
#pragma unroll
      for (int c = 0; c < 4; c++) a_stg[c] = *(const float4*)(Ap + 4 * c);
      const float* Bp = B + (size_t)(k0 + bRow) * ldb + colBase + bNb;
#pragma unroll
      for (int c = 0; c < 4; c++) b_stg[c] = *(const float4*)(Bp + 32 * c);
    }

    // mma on buffer t&1
    {
      const float* As = sm + (t & 1) * BUFSZ;
      const float* Bs = As + ASZ;
#pragma unroll
      for (int k8 = 0; k8 < 32; k8 += 8) {
        uint32_t af[4][4];
#pragma unroll
        for (int mt = 0; mt < 4; mt++) {
          int m0 = wm * 64 + mt * 16;
          af[mt][0] = __float_as_uint(As[(m0 + g) * ASTRIDE + k8 + tg]);
          af[mt][1] = __float_as_uint(As[(m0 + g + 8) * ASTRIDE + k8 + tg]);
          af[mt][2] = __float_as_uint(As[(m0 + g) * ASTRIDE + k8 + tg + 4]);
          af[mt][3] = __float_as_uint(As[(m0 + g + 8) * ASTRIDE + k8 + tg + 4]);
        }
        uint32_t bf[4][2];
#pragma unroll
        for (int nt = 0; nt < 4; nt++) {
          int n0 = wn * 32 + nt * 8;
          bf[nt][0] = __float_as_uint(Bs[(k8 + tg) * BSTRIDE + n0 + g]);
          bf[nt][1] = __float_as_uint(Bs[(k8 + tg + 4) * BSTRIDE + n0 + g]);
        }
#pragma unroll
        for (int mt = 0; mt < 4; mt++)
#pragma unroll
          for (int nt = 0; nt < 4; nt++) mma_tf32(acc[mt][nt], af[mt], bf[nt]);
      }
    }

    // store prefetched tile into other buffer
    if (t + 1 < nT) {
      float* As = sm + ((t + 1) & 1) * BUFSZ;
      float* Bs = As + ASZ;
#pragma unroll
      for (int c = 0; c < 4; c++) {
        float4 v = a_stg[c];
        float4 w =
            make_float4(f2tf32(v.x), f2tf32(v.y), f2tf32(v.z), f2tf32(v.w));
        *(float4*)&As[aRow * ASTRIDE + aKb + 4 * c] = w;
      }
#pragma unroll
      for (int c = 0; c < 4; c++) {
        float4 v = b_stg[c];
        float4 w =
            make_float4(f2tf32(v.x), f2tf32(v.y), f2tf32(v.z), f2tf32(v.w));
        *(float4*)&Bs[bRow * BSTRIDE + bNb + 32 * c] = w;
      }
      __syncthreads();
    }
  }

  // epilogue
#pragma unroll
  for (int mt = 0; mt < 4; mt++) {
    int row = rowBase + wm * 64 + mt * 16 + g;
#pragma unroll
    for (int nt = 0; nt < 4; nt++) {
      int col = colBase + wn * 32 + nt * 8 + tg * 2;
      float bv0 = bias[col], bv1 = bias[col + 1];
#pragma unroll
      for (int half = 0; half < 2; half++) {
        int r = row + half * 8;
        float v0 = acc[mt][nt][half * 2 + 0] + bv0;
        float v1 = acc[mt][nt][half * 2 + 1] + bv1;
        if (EPI == EPI_SIG) {
          v0 = 1.f / (1.f + __expf(-v0));
          v1 = 1.f / (1.f + __expf(-v1));
        } else if (EPI == EPI_SOFTPLUS) {
          v0 = (v0 > 20.f) ? v0 : log1pf(__expf(v0));
          v1 = (v1 > 20.f) ? v1 : log1pf(__expf(v1));
        }
        *(float2*)&C[(size_t)r * ldc + col] = make_float2(v0, v1);
      }
    }
  }
}

// ---------------------------------------------------------------------------
// SIMT fp32 GEMM (kept only for the skinny split-K xp GEMM, atomic epilogue)
// ---------------------------------------------------------------------------
template <int EPI>
__global__ __launch_bounds__(256) void gemm128(
    const float* __restrict__ A, const float* __restrict__ B,
    const float* __restrict__ bias, float* __restrict__ C,
    int M, int N, int K, int lda, int ldb, int ldc) {
  __shared__ float As[8][128];
  __shared__ float Bs[8][128];

  const int tid = threadIdx.x;
  const int rowBase = blockIdx.y * 128;
  const int colBase = blockIdx.x * 128;
  const int kChunk = K / gridDim.z;
  const int k0g = blockIdx.z * kChunk;
  const int kEnd = k0g + kChunk;

  const int aRow = tid >> 1;
  const int aCol = (tid & 1) * 4;
  const int bRow = tid >> 5;
  const int bCol = (tid & 31) * 4;

  const int tx = tid & 15;
  const int ty = tid >> 4;

  float acc[8][8];
#pragma unroll
  for (int i = 0; i < 8; i++)
#pragma unroll
    for (int j = 0; j < 8; j++) acc[i][j] = 0.f;

  for (int k0 = k0g; k0 < kEnd; k0 += 8) {
    float4 av = *(const float4*)(A + (size_t)(rowBase + aRow) * lda + k0 + aCol);
    As[aCol + 0][aRow] = av.x;
    As[aCol + 1][aRow] = av.y;
    As[aCol + 2][aRow] = av.z;
    As[aCol + 3][aRow] = av.w;
    float4 bv = make_float4(0.f, 0.f, 0.f, 0.f);
    if (colBase + bCol < N)
      bv = *(const float4*)(B + (size_t)(k0 + bRow) * ldb + colBase + bCol);
    *(float4*)&Bs[bRow][bCol] = bv;
    __syncthreads();

#pragma unroll
    for (int kk = 0; kk < 8; kk++) {
      float4 a01 = *(const float4*)&As[kk][ty * 8];
      float4 a23 = *(const float4*)&As[kk][ty * 8 + 4];
      float4 b01 = *(const float4*)&Bs[kk][tx * 8];
      float4 b23 = *(const float4*)&Bs[kk][tx * 8 + 4];
      float ar[8] = {a01.x, a01.y, a01.z, a01.w, a23.x, a23.y, a23.z, a23.w};
      float br[8] = {b01.x, b01.y, b01.z, b01.w, b23.x, b23.y, b23.z, b23.w};
#pragma unroll
      for (int i = 0; i < 8; i++)
#pragma unroll
        for (int j = 0; j < 8; j++) acc[i][j] = fmaf(ar[i], br[j], acc[i][j]);
    }
    __syncthreads();
  }

#pragma unroll
  for (int i = 0; i < 8; i++) {
    int row = rowBase + ty * 8 + i;
#pragma unroll
    for (int jv = 0; jv < 2; jv++) {
      int col = colBase + tx * 8 + jv * 4;
      if (col >= N) continue;
      if (EPI == EPI_ATOMIC) {
#pragma unroll
        for (int j = 0; j < 4; j++)
          atomicAdd(&C[(size_t)row * ldc + col + j], acc[i][jv * 4 + j]);
      } else {
        float4 out;
        float* o = &out.x;
#pragma unroll
        for (int j = 0; j < 4; j++) {
          float v = acc[i][jv * 4 + j] + bias[col + j];
          if (EPI == EPI_SIG) v = 1.f / (1.f + __expf(-v));
          o[j] = v;
        }
        *(float4*)&C[(size_t)row * ldc + col] = out;
      }
    }
  }
}

// ---------------------------------------------------------------------------
// Causal depthwise conv (K=4) + sigmoid
// ---------------------------------------------------------------------------
__global__ void conv_kernel(const float* __restrict__ uraw,
                            const float* __restrict__ conv_w,
                            const float* __restrict__ conv_b,
                            float* __restrict__ u) {
  int idx = blockIdx.x * blockDim.x + threadIdx.x;
  const int total = MM * MLPD;
  if (idx >= total) return;
  int d = idx % MLPD;
  int s = (idx / MLPD) % SS;
  float acc = conv_b[d];
#pragma unroll
  for (int k = 0; k < CONVK; k++) {
    int sp = s - (CONVK - 1) + k;
    if (sp >= 0) acc = fmaf(uraw[(size_t)idx + (size_t)(k - (CONVK - 1)) * MLPD],
                            conv_w[d * CONVK + k], acc);
  }
  u[idx] = 1.f / (1.f + __expf(-acc));
}

__global__ void zero_kernel(float* __restrict__ p, int n) {
  int i = blockIdx.x * blockDim.x + threadIdx.x;
  if (i < n) p[i] = 0.f;
}

// ---------------------------------------------------------------------------
// Selective scan. 16 lanes per channel (one per state n); shfl-tree reduce.
// ---------------------------------------------------------------------------
__global__ __launch_bounds__(128) void scan_kernel(
    const float* __restrict__ u, const float* __restrict__ delta,
    const float* __restrict__ xp, const float* __restrict__ A_log,
    const float* __restrict__ D_skip, const float* __restrict__ gate,
    float* __restrict__ yg) {
  const int lane_n = threadIdx.x & 15;
  const int dg = threadIdx.x >> 4;
  const int d = blockIdx.x * 8 + dg;
  const int b = blockIdx.y;

  const float A = -__expf(A_log[d * NST + lane_n]);
  const float Dv = D_skip[d];

  const size_t rowOff = (size_t)b * SS * MLPD + d;
  const float* __restrict__ xpB = xp + (size_t)b * SS * XPW;

  float h = 0.f;
#pragma unroll 4
  for (int t = 0; t < SS; t++) {
    size_t idx = rowOff + (size_t)t * MLPD;
    float dt = delta[idx];
    float ut = u[idx];
    float Bv = xpB[t * XPW + DTR + lane_n];
    float Cv = xpB[t * XPW + DTR + NST + lane_n];
    float a = __expf(dt * A);
    h = fmaf(a, h, dt * Bv * ut);
    float yp = h * Cv;
    yp += __shfl_xor_sync(0xFFFFFFFFu, yp, 8);
    yp += __shfl_xor_sync(0xFFFFFFFFu, yp, 4);
    yp += __shfl_xor_sync(0xFFFFFFFFu, yp, 2);
    yp += __shfl_xor_sync(0xFFFFFFFFu, yp, 1);
    if (lane_n == 0) {
      yg[idx] = (yp + ut * Dv) * gate[idx];
    }
  }
}

// ---------------------------------------------------------------------------
// Launch
// ---------------------------------------------------------------------------
extern "C" void kernel_launch(void* const* d_in, const int* in_sizes, int n_in,
                              void* d_out, int out_size) {
  const float* x = (const float*)d_in[0];
  const float* W1 = (const float*)d_in[1];
  const float* b1 = (const float*)d_in[2];
  const float* W2 = (const float*)d_in[3];
  const float* b2 = (const float*)d_in[4];
  const float* conv_w = (const float*)d_in[5];
  const float* conv_b = (const float*)d_in[6];
  const float* A_log = (const float*)d_in[7];
  const float* x_proj_w = (const float*)d_in[8];
  const float* dt_proj_w = (const float*)d_in[9];
  const float* dt_proj_b = (const float*)d_in[10];
  const float* D_skip = (const float*)d_in[11];
  const float* Wo = (const float*)d_in[12];
  const float* bo = (const float*)d_in[13];
  float* out = (float*)d_out;

  float *p_uraw, *p_u, *p_gate, *p_delta, *p_xp, *p_yg;
  cudaGetSymbolAddress((void**)&p_uraw, g_uraw);
  cudaGetSymbolAddress((void**)&p_u, g_u);
  cudaGetSymbolAddress((void**)&p_gate, g_gate);
  cudaGetSymbolAddress((void**)&p_delta, g_delta);
  cudaGetSymbolAddress((void**)&p_xp, g_xp);
  cudaGetSymbolAddress((void**)&p_yg, g_yg);

  // dynamic SMEM opt-in for tf32 GEMM (>48KB)
  cudaFuncSetAttribute(gemm_tf32<EPI_BIAS>,
                       cudaFuncAttributeMaxDynamicSharedMemorySize, GSMEM_BYTES);
  cudaFuncSetAttribute(gemm_tf32<EPI_SIG>,
                       cudaFuncAttributeMaxDynamicSharedMemorySize, GSMEM_BYTES);
  cudaFuncSetAttribute(gemm_tf32<EPI_SOFTPLUS>,
                       cudaFuncAttributeMaxDynamicSharedMemorySize, GSMEM_BYTES);

  // 1) u_raw = x @ W1 + b1      (M=4096, N=2048, K=1024)
  gemm_tf32<EPI_BIAS><<<dim3(MLPD / 128, MM / 128), 256, GSMEM_BYTES>>>(
      x, W1, b1, p_uraw, MM, MLPD, HID, HID, MLPD, MLPD);
  // 2) gate = sigmoid(x @ W2 + b2)
  gemm_tf32<EPI_SIG><<<dim3(MLPD / 128, MM / 128), 256, GSMEM_BYTES>>>(
      x, W2, b2, p_gate, MM, MLPD, HID, HID, MLPD, MLPD);
  // 3) u = sigmoid(causal_conv(u_raw))
  conv_kernel<<<(MM * MLPD + 255) / 256, 256>>>(p_uraw, conv_w, conv_b, p_u);
  // 4) xp = u @ x_proj_w   (split-K=8, atomic accumulate, SIMT)
  zero_kernel<<<(MM * XPW + 255) / 256, 256>>>(p_xp, MM * XPW);
  gemm128<EPI_ATOMIC><<<dim3(1, 32, 8), 256>>>(p_u, x_proj_w, nullptr, p_xp,
                                               MM, XPW, MLPD, MLPD, XPW, XPW);
  // 5) delta = softplus(xp[:, :64] @ dt_proj_w + dt_proj_b)  (K=64)
  gemm_tf32<EPI_SOFTPLUS><<<dim3(MLPD / 128, MM / 128), 256, GSMEM_BYTES>>>(
      p_xp, dt_proj_w, dt_proj_b, p_delta, MM, MLPD, DTR, XPW, MLPD, MLPD);
  // 6) selective scan -> yg = (y + u*D) * gate
  scan_kernel<<<dim3(MLPD / 8, BB), 128>>>(p_u, p_delta, p_xp, A_log, D_skip,
                                           p_gate, p_yg);
  // 7) out = yg @ Wo + bo   (M=4096, N=1024, K=2048)
  gemm_tf32<EPI_BIAS><<<dim3(HID / 128, MM / 128), 256, GSMEM_BYTES>>>(
      p_yg, Wo, bo, out, MM, HID, MLPD, MLPD, HID, HID);
}